// round 1
// baseline (speedup 1.0000x reference)
#include <cuda_runtime.h>
#include <cuda_bf16.h>
#include <cstdint>

// ---------------- static scratch (no allocs allowed) ----------------
#define MAXN 10240
#define MAXE 330240
#define MAXW 320   // ceil(MAXN/32)

__device__ float   g_P[MAXN * 256];
__device__ float   g_Q[MAXN * 256];
__device__ float   g_nbr[MAXN * 256];
__device__ float   g_f2[MAXN * 256];
__device__ float   g_S1[MAXN * 256];
__device__ float   g_T1[MAXN * 256];
__device__ unsigned g_AB[MAXN * MAXW];
__device__ unsigned g_RB[MAXN * MAXW];
__device__ int     g_rowptr[MAXN + 1];
__device__ int     g_cursor[MAXN];
__device__ int     g_degcnt[MAXN];
__device__ int     g_csrcol[MAXE];
__device__ float   g_cnt2[MAXN];

// ---------------- zero scratch that accumulates ----------------
__global__ void zero_kernel(int n, int words) {
    size_t total = (size_t)n * words;
    for (size_t idx = (size_t)blockIdx.x * blockDim.x + threadIdx.x; idx < total;
         idx += (size_t)gridDim.x * blockDim.x) {
        g_AB[idx] = 0u;
        if (idx < (size_t)n) g_degcnt[idx] = 0;
    }
}

// ---------------- per-edge: degree count + adjacency bitset ----------------
__global__ void edge_prep_kernel(const int* __restrict__ row, const int* __restrict__ col,
                                 int E, int words) {
    int e = blockIdx.x * blockDim.x + threadIdx.x;
    if (e >= E) return;
    int r = row[e], c = col[e];
    atomicAdd(&g_degcnt[r], 1);
    atomicOr(&g_AB[(size_t)r * words + (c >> 5)], 1u << (c & 31));
}

// ---------------- exclusive scan (single CTA, chunked Kogge-Stone) ----------------
__global__ void scan_kernel(int n) {
    __shared__ int s[1024];
    __shared__ int carry_s;
    int t = threadIdx.x;
    if (t == 0) carry_s = 0;
    __syncthreads();
    for (int base = 0; base < n; base += 1024) {
        int v = (base + t < n) ? g_degcnt[base + t] : 0;
        s[t] = v;
        __syncthreads();
        for (int off = 1; off < 1024; off <<= 1) {
            int add = (t >= off) ? s[t - off] : 0;
            __syncthreads();
            s[t] += add;
            __syncthreads();
        }
        int excl = carry_s + s[t] - v;
        if (base + t < n) { g_rowptr[base + t] = excl; g_cursor[base + t] = excl; }
        __syncthreads();
        if (t == 1023) carry_s += s[1023];
        __syncthreads();
    }
    if (t == 0) g_rowptr[n] = carry_s;
}

// ---------------- CSR scatter ----------------
__global__ void scatter_kernel(const int* __restrict__ row, const int* __restrict__ col, int E) {
    int e = blockIdx.x * blockDim.x + threadIdx.x;
    if (e >= E) return;
    int r = row[e];
    int p = atomicAdd(&g_cursor[r], 1);
    g_csrcol[p] = col[e];
}

// ---------------- 1-hop: nbr_mean + 2-hop reach bitset + cnt2 ----------------
// One CTA (256 thr) per node. Thread t owns output column t, bitset word t (and 256+t).
__global__ void hop1_kernel(const float* __restrict__ NT, int n, int words) {
    int i = blockIdx.x;
    int t = threadIdx.x;
    int t2 = 256 + t;
    int s0 = g_rowptr[i], s1 = g_rowptr[i + 1];
    unsigned w0 = 0u, w1 = 0u;
    float acc = 0.f;
    for (int p = s0; p < s1; p++) {
        int j = g_csrcol[p];
        const unsigned* abr = &g_AB[(size_t)j * words];
        if (t < words)  w0 |= abr[t];
        if (t2 < words) w1 |= abr[t2];
        acc += NT[(size_t)j * 256 + t];
    }
    // clear self bit
    int wi = i >> 5;
    unsigned sb = 1u << (i & 31);
    if (wi == t)  w0 &= ~sb;
    if (wi == t2) w1 &= ~sb;
    if (t < words)  g_RB[(size_t)i * words + t]  = w0;
    if (t2 < words) g_RB[(size_t)i * words + t2] = w1;

    int deg = s1 - s0;
    float inv = deg > 0 ? 1.f / (float)deg : 0.f;
    g_nbr[(size_t)i * 256 + t] = acc * inv;

    __shared__ int red[256];
    red[t] = __popc(w0) + __popc(w1);
    __syncthreads();
    for (int off = 128; off > 0; off >>= 1) {
        if (t < off) red[t] += red[t + off];
        __syncthreads();
    }
    if (t == 0) g_cnt2[i] = (float)red[0];
}

// ---------------- edge tokens: out2[e] = P[row[e]] + Q[col[e]] (be folded into P) ----------------
__global__ void edge_tok_kernel(const int* __restrict__ row, const int* __restrict__ col,
                                float* __restrict__ out2, int E) {
    long long idx = (long long)blockIdx.x * blockDim.x + threadIdx.x;
    long long total = (long long)E * 64;
    if (idx >= total) return;
    int e = (int)(idx >> 6);
    int q = (int)(idx & 63);
    int r = row[e], c = col[e];
    float4 a = reinterpret_cast<const float4*>(g_P)[(size_t)r * 64 + q];
    float4 b = reinterpret_cast<const float4*>(g_Q)[(size_t)c * 64 + q];
    float4 o;
    o.x = a.x + b.x; o.y = a.y + b.y; o.z = a.z + b.z; o.w = a.w + b.w;
    reinterpret_cast<float4*>(out2)[idx] = o;
}

// ---------------- feat2: smem-tiled bitset-masked row sum ----------------
// tile = 192 rows (6 bitset words) of node_tokens staged in 192KB smem.
// Each CTA owns 68 nodes, thread t owns column t, acc[68] in registers.
#define F2_MI 68
#define F2_TR 192
__global__ __launch_bounds__(256, 1)
void feat2_kernel(const float* __restrict__ NT, int n, int words) {
    extern __shared__ float tile[];  // F2_TR * 256 floats
    int t = threadIdx.x;
    int i0 = blockIdx.x * F2_MI;
    float acc[F2_MI];
#pragma unroll
    for (int m = 0; m < F2_MI; m++) acc[m] = 0.f;

    int ntiles = (words + 5) / 6;
    for (int tb = 0; tb < ntiles; tb++) {
        int k0 = tb * F2_TR;
        // load tile (192*64 float4 / 256 threads = 48 each)
        for (int v = t; v < F2_TR * 64; v += 256) {
            int r = v >> 6;
            int c = (v & 63) << 2;
            int k = k0 + r;
            float4 val = make_float4(0.f, 0.f, 0.f, 0.f);
            if (k < n) val = *reinterpret_cast<const float4*>(&NT[(size_t)k * 256 + c]);
            *reinterpret_cast<float4*>(&tile[r * 256 + c]) = val;
        }
        __syncthreads();
#pragma unroll
        for (int m = 0; m < F2_MI; m++) {
            int i = i0 + m;
            if (i < n) {
                const unsigned* rbr = &g_RB[(size_t)i * words + tb * 6];
#pragma unroll
                for (int wl = 0; wl < 6; wl++) {
                    int w = tb * 6 + wl;
                    unsigned mask = (w < words) ? rbr[wl] : 0u;
                    while (mask) {
                        int b = __ffs(mask) - 1;
                        mask &= mask - 1;
                        acc[m] += tile[((wl << 5) + b) * 256 + t];
                    }
                }
            }
        }
        __syncthreads();
    }
#pragma unroll
    for (int m = 0; m < F2_MI; m++) {
        int i = i0 + m;
        if (i < n) {
            float c = g_cnt2[i];
            float inv = c > 0.f ? 1.f / c : 0.f;
            g_f2[(size_t)i * 256 + t] = acc[m] * inv;
        }
    }
}

// ---------------- SGEMM: C[M,256] = act( [A0|A1|A2][M,K] @ W[K,256] + bias ) ----------------
// BM=128, BN=64, BK=16, 256 threads, 8x4 register tile.
__global__ __launch_bounds__(256)
void sgemm_kernel(const float* __restrict__ A0, const float* __restrict__ A1,
                  const float* __restrict__ A2, int nblk,
                  const float* __restrict__ W, const float* __restrict__ bias,
                  float* __restrict__ C, int M, int relu) {
    __shared__ float As[16 * 132];  // [BK][BM] padded
    __shared__ float Bs[16 * 64];   // [BK][BN]
    int tid = threadIdx.x;
    int tx = tid & 15;   // col group
    int ty = tid >> 4;   // row group
    int row0 = blockIdx.y * 128;
    int col0 = blockIdx.x * 64;
    const float* Ab[3] = {A0, A1, A2};
    int K = nblk << 8;

    float acc[8][4];
#pragma unroll
    for (int i = 0; i < 8; i++)
#pragma unroll
        for (int j = 0; j < 4; j++) acc[i][j] = 0.f;

    int la_r = tid >> 2;
    int la_c = (tid & 3) << 2;
    int lb_r = tid >> 4;
    int lb_c = (tid & 15) << 2;

    for (int kt = 0; kt < K; kt += 16) {
        const float* Ap = Ab[kt >> 8] + (kt & 255);
#pragma unroll
        for (int pass = 0; pass < 2; pass++) {
            int r = la_r + pass * 64;
            int gr = row0 + r;
            float4 v = make_float4(0.f, 0.f, 0.f, 0.f);
            if (gr < M) v = *reinterpret_cast<const float4*>(&Ap[(size_t)gr * 256 + la_c]);
            As[(la_c + 0) * 132 + r] = v.x;
            As[(la_c + 1) * 132 + r] = v.y;
            As[(la_c + 2) * 132 + r] = v.z;
            As[(la_c + 3) * 132 + r] = v.w;
        }
        *reinterpret_cast<float4*>(&Bs[lb_r * 64 + lb_c]) =
            *reinterpret_cast<const float4*>(&W[(size_t)(kt + lb_r) * 256 + col0 + lb_c]);
        __syncthreads();
#pragma unroll
        for (int kk = 0; kk < 16; kk++) {
            float a0[4], a1[4], b[4];
            *reinterpret_cast<float4*>(a0) = *reinterpret_cast<float4*>(&As[kk * 132 + ty * 4]);
            *reinterpret_cast<float4*>(a1) = *reinterpret_cast<float4*>(&As[kk * 132 + 64 + ty * 4]);
            *reinterpret_cast<float4*>(b)  = *reinterpret_cast<float4*>(&Bs[kk * 64 + tx * 4]);
#pragma unroll
            for (int i = 0; i < 4; i++)
#pragma unroll
                for (int j = 0; j < 4; j++) {
                    acc[i][j]     += a0[i] * b[j];
                    acc[i + 4][j] += a1[i] * b[j];
                }
        }
        __syncthreads();
    }

    float bv[4] = {0.f, 0.f, 0.f, 0.f};
    if (bias) {
        *reinterpret_cast<float4*>(bv) =
            *reinterpret_cast<const float4*>(&bias[col0 + tx * 4]);
    }
#pragma unroll
    for (int g = 0; g < 2; g++) {
#pragma unroll
        for (int i = 0; i < 4; i++) {
            int row = row0 + g * 64 + ty * 4 + i;
            if (row < M) {
                float o[4];
#pragma unroll
                for (int j = 0; j < 4; j++) {
                    float v = acc[g * 4 + i][j] + bv[j];
                    if (relu) v = v > 0.f ? v : 0.f;
                    o[j] = v;
                }
                *reinterpret_cast<float4*>(&C[(size_t)row * 256 + col0 + tx * 4]) =
                    *reinterpret_cast<float4*>(o);
            }
        }
    }
}

// ---------------- launch ----------------
extern "C" void kernel_launch(void* const* d_in, const int* in_sizes, int n_in,
                              void* d_out, int out_size) {
    const float* x    = (const float*)d_in[0];
    const int*   ei   = (const int*)d_in[1];
    const float* Wn   = (const float*)d_in[2];
    const float* bn   = (const float*)d_in[3];
    const float* We   = (const float*)d_in[4];
    const float* be   = (const float*)d_in[5];
    const float* Ws1  = (const float*)d_in[6];
    const float* bs1  = (const float*)d_in[7];
    const float* Ws2  = (const float*)d_in[8];
    const float* bs2  = (const float*)d_in[9];
    const float* Wh1  = (const float*)d_in[10];
    const float* bh1  = (const float*)d_in[11];
    const float* Wh2  = (const float*)d_in[12];
    const float* bh2  = (const float*)d_in[13];

    const int H = in_sizes[3];            // 256
    const int F = in_sizes[2] / H;        // 256
    const int N = in_sizes[0] / F;
    const int E = in_sizes[1] / 2;
    const int WORDS = (N + 31) / 32;
    (void)n_in; (void)out_size;

    const int* row = ei;
    const int* col = ei + E;

    float* out1 = (float*)d_out;                       // node_tokens
    float* out2 = out1 + (size_t)N * 256;              // edge_tokens
    float* out3 = out2 + (size_t)E * 256;              // subgraph_tokens
    float* out4 = out3 + (size_t)N * 256;              // neighborhood_tokens

    float *pP, *pQ, *pNbr, *pF2, *pS1, *pT1;
    cudaGetSymbolAddress((void**)&pP,  g_P);
    cudaGetSymbolAddress((void**)&pQ,  g_Q);
    cudaGetSymbolAddress((void**)&pNbr, g_nbr);
    cudaGetSymbolAddress((void**)&pF2, g_f2);
    cudaGetSymbolAddress((void**)&pS1, g_S1);
    cudaGetSymbolAddress((void**)&pT1, g_T1);

    static bool attr_done = false;
    cudaFuncSetAttribute(feat2_kernel, cudaFuncAttributeMaxDynamicSharedMemorySize,
                         F2_TR * 256 * sizeof(float));
    (void)attr_done;

    dim3 gblk(256);
    dim3 ggrid(4, (N + 127) / 128);

    // zero accumulating scratch
    zero_kernel<<<512, 256>>>(N, WORDS);

    // tokenizer GEMMs: node_tokens -> out1, P = x@We_top + be, Q = x@We_bot
    sgemm_kernel<<<ggrid, gblk>>>(x, nullptr, nullptr, 1, Wn, bn, out1, N, 0);
    sgemm_kernel<<<ggrid, gblk>>>(x, nullptr, nullptr, 1, We, be, pP, N, 0);
    sgemm_kernel<<<ggrid, gblk>>>(x, nullptr, nullptr, 1, We + (size_t)F * 256, nullptr, pQ, N, 0);

    // graph structure
    int eb = (E + 255) / 256;
    edge_prep_kernel<<<eb, 256>>>(row, col, E, WORDS);
    scan_kernel<<<1, 1024>>>(N);
    scatter_kernel<<<eb, 256>>>(row, col, E);

    // 1-hop mean + 2-hop reach bitsets
    hop1_kernel<<<N, 256>>>(out1, N, WORDS);

    // edge tokens
    long long etot = (long long)E * 64;
    int etb = (int)((etot + 255) / 256);
    edge_tok_kernel<<<etb, 256>>>(row, col, out2, E);

    // feat2 (2-hop unique mean)
    int f2grid = (N + F2_MI - 1) / F2_MI;
    feat2_kernel<<<f2grid, 256, F2_TR * 256 * sizeof(float)>>>(out1, N, WORDS);

    // subgraph MLP
    sgemm_kernel<<<ggrid, gblk>>>(out1, pNbr, nullptr, 2, Ws1, bs1, pS1, N, 1);
    sgemm_kernel<<<ggrid, gblk>>>(pS1, nullptr, nullptr, 1, Ws2, bs2, out3, N, 0);

    // neighborhood MLP
    sgemm_kernel<<<ggrid, gblk>>>(out1, pNbr, pF2, 3, Wh1, bh1, pT1, N, 1);
    sgemm_kernel<<<ggrid, gblk>>>(pT1, nullptr, nullptr, 1, Wh2, bh2, out4, N, 0);
}

// round 3
// speedup vs baseline: 3.2500x; 3.2500x over previous
#include <cuda_runtime.h>
#include <cuda_bf16.h>
#include <cstdint>

// ---------------- static scratch (no allocs allowed) ----------------
#define MAXN 10240
#define MAXE 330240
#define MAXW 320   // ceil(MAXN/32)

__device__ float   g_P[MAXN * 256];
__device__ float   g_Q[MAXN * 256];
__device__ float   g_nbr[MAXN * 256];
__device__ float   g_f2[MAXN * 256];
__device__ float   g_S1[MAXN * 256];
__device__ float   g_T1[MAXN * 256];
__device__ unsigned g_AB[MAXN * MAXW];
__device__ unsigned g_RB[MAXN * MAXW];
__device__ int     g_rowptr[MAXN + 1];
__device__ int     g_cursor[MAXN];
__device__ int     g_degcnt[MAXN];
__device__ int     g_csrcol[MAXE];
__device__ float   g_cnt2[MAXN];

// ---------------- zero scratch that accumulates ----------------
__global__ void zero_kernel(int n, int words) {
    size_t total = (size_t)n * words;
    for (size_t idx = (size_t)blockIdx.x * blockDim.x + threadIdx.x; idx < total;
         idx += (size_t)gridDim.x * blockDim.x) {
        g_AB[idx] = 0u;
        if (idx < (size_t)n) g_degcnt[idx] = 0;
    }
}

// ---------------- per-edge: degree count + adjacency bitset ----------------
__global__ void edge_prep_kernel(const int* __restrict__ row, const int* __restrict__ col,
                                 int E, int words) {
    int e = blockIdx.x * blockDim.x + threadIdx.x;
    if (e >= E) return;
    int r = row[e], c = col[e];
    atomicAdd(&g_degcnt[r], 1);
    atomicOr(&g_AB[(size_t)r * words + (c >> 5)], 1u << (c & 31));
}

// ---------------- exclusive scan (single CTA, chunked Kogge-Stone) ----------------
__global__ void scan_kernel(int n) {
    __shared__ int s[1024];
    __shared__ int carry_s;
    int t = threadIdx.x;
    if (t == 0) carry_s = 0;
    __syncthreads();
    for (int base = 0; base < n; base += 1024) {
        int v = (base + t < n) ? g_degcnt[base + t] : 0;
        s[t] = v;
        __syncthreads();
        for (int off = 1; off < 1024; off <<= 1) {
            int add = (t >= off) ? s[t - off] : 0;
            __syncthreads();
            s[t] += add;
            __syncthreads();
        }
        int excl = carry_s + s[t] - v;
        if (base + t < n) { g_rowptr[base + t] = excl; g_cursor[base + t] = excl; }
        __syncthreads();
        if (t == 1023) carry_s += s[1023];
        __syncthreads();
    }
    if (t == 0) g_rowptr[n] = carry_s;
}

// ---------------- CSR scatter ----------------
__global__ void scatter_kernel(const int* __restrict__ row, const int* __restrict__ col, int E) {
    int e = blockIdx.x * blockDim.x + threadIdx.x;
    if (e >= E) return;
    int r = row[e];
    int p = atomicAdd(&g_cursor[r], 1);
    g_csrcol[p] = col[e];
}

// ---------------- 1-hop: nbr_mean + 2-hop reach bitset + cnt2 ----------------
__global__ void hop1_kernel(const float* __restrict__ NT, int n, int words) {
    int i = blockIdx.x;
    int t = threadIdx.x;
    int t2 = 256 + t;
    int s0 = g_rowptr[i], s1 = g_rowptr[i + 1];
    unsigned w0 = 0u, w1 = 0u;
    float acc = 0.f;
    for (int p = s0; p < s1; p++) {
        int j = g_csrcol[p];
        const unsigned* abr = &g_AB[(size_t)j * words];
        if (t < words)  w0 |= abr[t];
        if (t2 < words) w1 |= abr[t2];
        acc += NT[(size_t)j * 256 + t];
    }
    int wi = i >> 5;
    unsigned sb = 1u << (i & 31);
    if (wi == t)  w0 &= ~sb;
    if (wi == t2) w1 &= ~sb;
    if (t < words)  g_RB[(size_t)i * words + t]  = w0;
    if (t2 < words) g_RB[(size_t)i * words + t2] = w1;

    int deg = s1 - s0;
    float inv = deg > 0 ? 1.f / (float)deg : 0.f;
    g_nbr[(size_t)i * 256 + t] = acc * inv;

    __shared__ int red[256];
    red[t] = __popc(w0) + __popc(w1);
    __syncthreads();
    for (int off = 128; off > 0; off >>= 1) {
        if (t < off) red[t] += red[t + off];
        __syncthreads();
    }
    if (t == 0) g_cnt2[i] = (float)red[0];
}

// ---------------- edge tokens: out2[e] = P[row[e]] + Q[col[e]] ----------------
__global__ void edge_tok_kernel(const int* __restrict__ row, const int* __restrict__ col,
                                float* __restrict__ out2, int E) {
    long long idx = (long long)blockIdx.x * blockDim.x + threadIdx.x;
    long long total = (long long)E * 64;
    if (idx >= total) return;
    int e = (int)(idx >> 6);
    int q = (int)(idx & 63);
    int r = row[e], c = col[e];
    float4 a = reinterpret_cast<const float4*>(g_P)[(size_t)r * 64 + q];
    float4 b = reinterpret_cast<const float4*>(g_Q)[(size_t)c * 64 + q];
    float4 o;
    o.x = a.x + b.x; o.y = a.y + b.y; o.z = a.z + b.z; o.w = a.w + b.w;
    reinterpret_cast<float4*>(out2)[idx] = o;
}

// ---------------- feat2 v2.1: smem-staged masks + float4 column ownership ----------------
// Tile = 192 rows of node_tokens in smem. Per tile, stage the 68x6=408 mask
// words into smem ONCE via a strided loop (v2 bug: single `if (t<408)` with
// 256 threads left words 256..407 stale -> wrong output 3).
// 8 warps = 4 node-groups x 2 column-halves; each thread owns 4 columns (float4).
#define F2_MI 68
#define F2_TR 192
#define F2_NG 17   // nodes per group (68/4)
__global__ __launch_bounds__(256, 1)
void feat2_kernel(const float* __restrict__ NT, int n, int words) {
    extern __shared__ float tile[];                      // F2_TR*256 floats
    unsigned* smask = (unsigned*)(tile + F2_TR * 256);   // F2_MI*6 words

    int t = threadIdx.x;
    int w = t >> 5;
    int l = t & 31;
    int g = w >> 1;          // node group 0..3
    int h = w & 1;           // column half
    int c0 = h * 128 + l * 4;
    int i0 = blockIdx.x * F2_MI;

    float acc[F2_NG][4];
#pragma unroll
    for (int k = 0; k < F2_NG; k++) {
        acc[k][0] = 0.f; acc[k][1] = 0.f; acc[k][2] = 0.f; acc[k][3] = 0.f;
    }

    int ntiles = (words + 5) / 6;
    for (int tb = 0; tb < ntiles; tb++) {
        int k0 = tb * F2_TR;
        // cooperative tile load: 192 rows x 256 cols
        for (int v = t; v < F2_TR * 64; v += 256) {
            int r = v >> 6;
            int c = (v & 63) << 2;
            int kk = k0 + r;
            float4 val = make_float4(0.f, 0.f, 0.f, 0.f);
            if (kk < n) val = *reinterpret_cast<const float4*>(&NT[(size_t)kk * 256 + c]);
            *reinterpret_cast<float4*>(&tile[r * 256 + c]) = val;
        }
        // stage masks for this window: 68 nodes x 6 words = 408 (strided!)
        for (int v = t; v < F2_MI * 6; v += 256) {
            int m = v / 6, wl = v % 6;
            int i = i0 + m;
            int wd = tb * 6 + wl;
            smask[v] = (i < n && wd < words) ? g_RB[(size_t)i * words + wd] : 0u;
        }
        __syncthreads();
#pragma unroll
        for (int k = 0; k < F2_NG; k++) {
            int m = g * F2_NG + k;
#pragma unroll
            for (int wl = 0; wl < 6; wl++) {
                unsigned mask = smask[m * 6 + wl];
                while (mask) {
                    int b = __ffs(mask) - 1;
                    mask &= mask - 1;
                    const float4 v =
                        *reinterpret_cast<const float4*>(&tile[((wl << 5) + b) * 256 + c0]);
                    acc[k][0] += v.x; acc[k][1] += v.y;
                    acc[k][2] += v.z; acc[k][3] += v.w;
                }
            }
        }
        __syncthreads();
    }
#pragma unroll
    for (int k = 0; k < F2_NG; k++) {
        int i = i0 + g * F2_NG + k;
        if (i < n) {
            float c = g_cnt2[i];
            float inv = c > 0.f ? 1.f / c : 0.f;
            float4 o;
            o.x = acc[k][0] * inv; o.y = acc[k][1] * inv;
            o.z = acc[k][2] * inv; o.w = acc[k][3] * inv;
            *reinterpret_cast<float4*>(&g_f2[(size_t)i * 256 + c0]) = o;
        }
    }
}

// ---------------- SGEMM v2: 128x128 tile, 8x8 micro-tile ----------------
// C[M,256] = act( [A0|A1|A2][M,K] @ W[K,256] + bias )
__global__ __launch_bounds__(256, 2)
void sgemm_kernel(const float* __restrict__ A0, const float* __restrict__ A1,
                  const float* __restrict__ A2, int nblk,
                  const float* __restrict__ W, const float* __restrict__ bias,
                  float* __restrict__ C, int M, int relu) {
    __shared__ float As[16 * 132];   // [BK][BM] transposed, padded
    __shared__ float Bs[16 * 128];   // [BK][BN]
    int tid = threadIdx.x;
    int tx = tid & 15;
    int ty = tid >> 4;
    int row0 = blockIdx.y * 128;
    int col0 = blockIdx.x * 128;
    const float* Ab[3] = {A0, A1, A2};
    int K = nblk << 8;

    float acc[8][8];
#pragma unroll
    for (int i = 0; i < 8; i++)
#pragma unroll
        for (int j = 0; j < 8; j++) acc[i][j] = 0.f;

    int ar = tid >> 2;
    int ac = (tid & 3) << 2;
    int br = tid >> 5;
    int bc = (tid & 31) << 2;

    for (int kt = 0; kt < K; kt += 16) {
        const float* Ap = Ab[kt >> 8] + (kt & 255);
#pragma unroll
        for (int p = 0; p < 2; p++) {
            int r = ar + p * 64;
            int gr = row0 + r;
            float4 v = make_float4(0.f, 0.f, 0.f, 0.f);
            if (gr < M) v = *reinterpret_cast<const float4*>(&Ap[(size_t)gr * 256 + ac]);
            As[(ac + 0) * 132 + r] = v.x;
            As[(ac + 1) * 132 + r] = v.y;
            As[(ac + 2) * 132 + r] = v.z;
            As[(ac + 3) * 132 + r] = v.w;
        }
#pragma unroll
        for (int p = 0; p < 2; p++) {
            int kk = br + p * 8;
            *reinterpret_cast<float4*>(&Bs[kk * 128 + bc]) =
                *reinterpret_cast<const float4*>(&W[(size_t)(kt + kk) * 256 + col0 + bc]);
        }
        __syncthreads();
#pragma unroll
        for (int kk = 0; kk < 16; kk++) {
            float a[8], b[8];
            *reinterpret_cast<float4*>(&a[0]) = *reinterpret_cast<float4*>(&As[kk * 132 + ty * 4]);
            *reinterpret_cast<float4*>(&a[4]) = *reinterpret_cast<float4*>(&As[kk * 132 + 64 + ty * 4]);
            *reinterpret_cast<float4*>(&b[0]) = *reinterpret_cast<float4*>(&Bs[kk * 128 + tx * 4]);
            *reinterpret_cast<float4*>(&b[4]) = *reinterpret_cast<float4*>(&Bs[kk * 128 + 64 + tx * 4]);
#pragma unroll
            for (int i = 0; i < 8; i++)
#pragma unroll
                for (int j = 0; j < 8; j++)
                    acc[i][j] += a[i] * b[j];
        }
        __syncthreads();
    }

    float bv[8] = {0.f, 0.f, 0.f, 0.f, 0.f, 0.f, 0.f, 0.f};
    if (bias) {
        *reinterpret_cast<float4*>(&bv[0]) =
            *reinterpret_cast<const float4*>(&bias[col0 + tx * 4]);
        *reinterpret_cast<float4*>(&bv[4]) =
            *reinterpret_cast<const float4*>(&bias[col0 + 64 + tx * 4]);
    }
#pragma unroll
    for (int gi = 0; gi < 2; gi++) {
#pragma unroll
        for (int i = 0; i < 4; i++) {
            int row = row0 + gi * 64 + ty * 4 + i;
            if (row < M) {
#pragma unroll
                for (int gj = 0; gj < 2; gj++) {
                    float o[4];
#pragma unroll
                    for (int j = 0; j < 4; j++) {
                        float v = acc[gi * 4 + i][gj * 4 + j] + bv[gj * 4 + j];
                        if (relu) v = v > 0.f ? v : 0.f;
                        o[j] = v;
                    }
                    *reinterpret_cast<float4*>(&C[(size_t)row * 256 + col0 + gj * 64 + tx * 4]) =
                        *reinterpret_cast<float4*>(o);
                }
            }
        }
    }
}

// ---------------- launch ----------------
extern "C" void kernel_launch(void* const* d_in, const int* in_sizes, int n_in,
                              void* d_out, int out_size) {
    const float* x    = (const float*)d_in[0];
    const int*   ei   = (const int*)d_in[1];
    const float* Wn   = (const float*)d_in[2];
    const float* bn   = (const float*)d_in[3];
    const float* We   = (const float*)d_in[4];
    const float* be   = (const float*)d_in[5];
    const float* Ws1  = (const float*)d_in[6];
    const float* bs1  = (const float*)d_in[7];
    const float* Ws2  = (const float*)d_in[8];
    const float* bs2  = (const float*)d_in[9];
    const float* Wh1  = (const float*)d_in[10];
    const float* bh1  = (const float*)d_in[11];
    const float* Wh2  = (const float*)d_in[12];
    const float* bh2  = (const float*)d_in[13];

    const int H = in_sizes[3];            // 256
    const int F = in_sizes[2] / H;        // 256
    const int N = in_sizes[0] / F;
    const int E = in_sizes[1] / 2;
    const int WORDS = (N + 31) / 32;
    (void)n_in; (void)out_size;

    const int* row = ei;
    const int* col = ei + E;

    float* out1 = (float*)d_out;                       // node_tokens
    float* out2 = out1 + (size_t)N * 256;              // edge_tokens
    float* out3 = out2 + (size_t)E * 256;              // subgraph_tokens
    float* out4 = out3 + (size_t)N * 256;              // neighborhood_tokens

    float *pP, *pQ, *pNbr, *pF2, *pS1, *pT1;
    cudaGetSymbolAddress((void**)&pP,  g_P);
    cudaGetSymbolAddress((void**)&pQ,  g_Q);
    cudaGetSymbolAddress((void**)&pNbr, g_nbr);
    cudaGetSymbolAddress((void**)&pF2, g_f2);
    cudaGetSymbolAddress((void**)&pS1, g_S1);
    cudaGetSymbolAddress((void**)&pT1, g_T1);

    size_t f2_smem = (size_t)(F2_TR * 256) * sizeof(float) + (F2_MI * 6) * sizeof(unsigned);
    cudaFuncSetAttribute(feat2_kernel, cudaFuncAttributeMaxDynamicSharedMemorySize,
                         (int)f2_smem);

    dim3 gblk(256);
    dim3 ggrid(2, (N + 127) / 128);   // 128-wide column tiles over 256 cols

    // zero accumulating scratch
    zero_kernel<<<512, 256>>>(N, WORDS);

    // tokenizer GEMMs: node_tokens -> out1, P = x@We_top + be, Q = x@We_bot
    sgemm_kernel<<<ggrid, gblk>>>(x, nullptr, nullptr, 1, Wn, bn, out1, N, 0);
    sgemm_kernel<<<ggrid, gblk>>>(x, nullptr, nullptr, 1, We, be, pP, N, 0);
    sgemm_kernel<<<ggrid, gblk>>>(x, nullptr, nullptr, 1, We + (size_t)F * 256, nullptr, pQ, N, 0);

    // graph structure
    int eb = (E + 255) / 256;
    edge_prep_kernel<<<eb, 256>>>(row, col, E, WORDS);
    scan_kernel<<<1, 1024>>>(N);
    scatter_kernel<<<eb, 256>>>(row, col, E);

    // 1-hop mean + 2-hop reach bitsets
    hop1_kernel<<<N, 256>>>(out1, N, WORDS);

    // edge tokens
    long long etot = (long long)E * 64;
    int etb = (int)((etot + 255) / 256);
    edge_tok_kernel<<<etb, 256>>>(row, col, out2, E);

    // feat2 (2-hop unique mean)
    int f2grid = (N + F2_MI - 1) / F2_MI;
    feat2_kernel<<<f2grid, 256, f2_smem>>>(out1, N, WORDS);

    // subgraph MLP
    sgemm_kernel<<<ggrid, gblk>>>(out1, pNbr, nullptr, 2, Ws1, bs1, pS1, N, 1);
    sgemm_kernel<<<ggrid, gblk>>>(pS1, nullptr, nullptr, 1, Ws2, bs2, out3, N, 0);

    // neighborhood MLP
    sgemm_kernel<<<ggrid, gblk>>>(out1, pNbr, pF2, 3, Wh1, bh1, pT1, N, 1);
    sgemm_kernel<<<ggrid, gblk>>>(pT1, nullptr, nullptr, 1, Wh2, bh2, out4, N, 0);
}